// round 3
// baseline (speedup 1.0000x reference)
#include <cuda_runtime.h>

// E3nnSimpleNodeBlock: out = TensorSquare(feats+msgs), N=131072, MUL=16.
// Round 2: f32x2 node-pair compute, px1 in regs, x0/stage-2 operands in SMEM,
// splatted weights in global ([w][v]-major, 8KB slab per w -> L1 friendly),
// __launch_bounds__(128,3) for 12 warps/SM with no register spills.

#define T 128
#define NODES_PER_BLOCK 256
#define NNODES 131072

// Splatted, pre-scaled weights. Layout: [w][v][32 ulonglong2], each ulonglong2 =
// two consecutive splatted weights of slot order [000 u0..15 | 110 | 101 | 112].
// 16*16*32*16B = 128 KB.
__device__ ulonglong2 PW2[16 * 16 * 32];

typedef unsigned long long u64;

// ---------- f32x2 helpers ----------
__device__ __forceinline__ u64 f2fma(u64 a, u64 b, u64 c) {
    u64 d;
    asm("fma.rn.f32x2 %0, %1, %2, %3;" : "=l"(d) : "l"(a), "l"(b), "l"(c));
    return d;
}
__device__ __forceinline__ u64 f2add(u64 a, u64 b) {
    u64 d;
    asm("add.rn.f32x2 %0, %1, %2;" : "=l"(d) : "l"(a), "l"(b));
    return d;
}
__device__ __forceinline__ u64 f2mul(u64 a, u64 b) {
    u64 d;
    asm("mul.rn.f32x2 %0, %1, %2;" : "=l"(d) : "l"(a), "l"(b));
    return d;
}
__device__ __forceinline__ u64 fpack(float lo, float hi) {
    u64 d;
    asm("mov.b64 %0, {%1, %2};" : "=l"(d) : "f"(lo), "f"(hi));
    return d;
}
__device__ __forceinline__ void funpack(u64 p, float& lo, float& hi) {
    asm("mov.b64 {%0, %1}, %2;" : "=f"(lo), "=f"(hi) : "l"(p));
}

// ---------- weight prep: transpose + scale + splat, [w][v][slot] ----------
__global__ void prep_kernel(const float* __restrict__ w000, const float* __restrict__ w101,
                            const float* __restrict__ w110, const float* __restrict__ w112) {
    int idx = blockIdx.x * blockDim.x + threadIdx.x;   // 0 .. 16383
    if (idx >= 16 * 16 * 64) return;
    int w = idx >> 10;
    int v = (idx >> 6) & 15;
    int slot = idx & 63;
    int which = slot >> 4, u = slot & 15;
    int widx = u * 256 + v * 16 + w;                   // w[u][v][w], row-major
    const float A000 = 0.04419417382415922f;           // sqrt(1/(2*MUL*MUL))
    const float A110 = 0.02551551815399144f;           // A000/sqrt(3)
    const float A101 = 0.0625f;                        // sqrt(3/MUL^2)/sqrt(3)
    const float A112 = 0.13975424859373686f;           // sqrt(5)/16
    float val;
    if (which == 0)      val = A000 * w000[widx];
    else if (which == 1) val = A110 * w110[widx];
    else if (which == 2) val = A101 * w101[widx];
    else                 val = A112 * w112[widx];
    reinterpret_cast<float2*>(PW2)[idx] = make_float2(val, val);   // splat
}

// ---------- main kernel ----------
__global__ __launch_bounds__(T, 3) void e3nn_kernel(const float* __restrict__ feats,
                                                    const float* __restrict__ msgs,
                                                    float* __restrict__ out) {
    // SMEM: xs0u (x0 pairs, u64[16*T]) | xsA ({x1[v][0],x1[v][1]}, ull2[16*T]) | xsB (x1[v][2], u64[16*T])
    extern __shared__ u64 sm[];
    u64* xs0u = sm;                                       // 16*T u64
    ulonglong2* xsA = reinterpret_cast<ulonglong2*>(sm + 16 * T);  // 16*T ull2
    u64* xsB = sm + 16 * T + 32 * T;                      // 16*T u64

    const int t = threadIdx.x;
    const int nA = blockIdx.x * NODES_PER_BLOCK + t;
    const int nB = nA + T;

    // ---- load x = feats + msgs for both nodes, pack into f32x2 ----
    u64 px1[16][3];
    {
        float xA[64], xB[64];
        const float4* fA = reinterpret_cast<const float4*>(feats) + nA * 16;
        const float4* mA = reinterpret_cast<const float4*>(msgs) + nA * 16;
        const float4* fB = reinterpret_cast<const float4*>(feats) + nB * 16;
        const float4* mB = reinterpret_cast<const float4*>(msgs) + nB * 16;
#pragma unroll
        for (int q = 0; q < 16; ++q) {
            float4 f = fA[q], m = mA[q];
            xA[4 * q + 0] = f.x + m.x; xA[4 * q + 1] = f.y + m.y;
            xA[4 * q + 2] = f.z + m.z; xA[4 * q + 3] = f.w + m.w;
        }
#pragma unroll
        for (int q = 0; q < 16; ++q) {
            float4 f = fB[q], m = mB[q];
            xB[4 * q + 0] = f.x + m.x; xB[4 * q + 1] = f.y + m.y;
            xB[4 * q + 2] = f.z + m.z; xB[4 * q + 3] = f.w + m.w;
        }
        // x0 pairs -> SMEM only (not kept in regs)
#pragma unroll
        for (int v = 0; v < 16; ++v) xs0u[v * T + t] = fpack(xA[v], xB[v]);
#pragma unroll
        for (int v = 0; v < 16; ++v) {
#pragma unroll
            for (int i = 0; i < 3; ++i) px1[v][i] = fpack(xA[16 + 3 * v + i], xB[16 + 3 * v + i]);
        }
    }
    // stage-2 operand stash (thread-private slots; no sync needed)
#pragma unroll
    for (int v = 0; v < 16; ++v) {
        xsA[v * T + t] = make_ulonglong2(px1[v][0], px1[v][1]);
        xsB[v * T + t] = px1[v][2];
    }

    float* outA = out + (long)nA * 144;
    float* outB = out + (long)nB * 144;

#pragma unroll 1
    for (int w = 0; w < 16; ++w) {
        const ulonglong2* __restrict__ pwbase = PW2 + w * (16 * 32);

        u64 acc00 = 0, acc01 = 0;              // out0 paths (000 / 110)
        u64 a10 = 0, a11 = 0, a12 = 0;         // out1 k=0..2
        u64 P0 = 0, P1 = 0, P2 = 0;            // out2 diagonal sums
        u64 Q01 = 0, Q02 = 0, Q12 = 0;         // out2 cross sums

#pragma unroll 1
        for (int v = 0; v < 16; ++v) {
            const ulonglong2* __restrict__ pwv = pwbase + v * 32;

            u64 s000 = 0;
            u64 s110_0 = 0, s110_1 = 0, s110_2 = 0;
            u64 s101_0 = 0, s101_1 = 0, s101_2 = 0;
            u64 s112_0 = 0, s112_1 = 0, s112_2 = 0;

#pragma unroll
            for (int g = 0; g < 8; ++g) {                 // w000 (x0 from SMEM, volatile: no hoist)
                ulonglong2 q = pwv[g];
                u64 x0a = *(volatile const u64*)&xs0u[(2 * g + 0) * T + t];
                u64 x0b = *(volatile const u64*)&xs0u[(2 * g + 1) * T + t];
                s000 = f2fma(q.x, x0a, s000);
                s000 = f2fma(q.y, x0b, s000);
            }
#pragma unroll
            for (int g = 0; g < 8; ++g) {                 // w110
                ulonglong2 q = pwv[8 + g];
                s110_0 = f2fma(q.x, px1[2 * g][0], s110_0);
                s110_1 = f2fma(q.x, px1[2 * g][1], s110_1);
                s110_2 = f2fma(q.x, px1[2 * g][2], s110_2);
                s110_0 = f2fma(q.y, px1[2 * g + 1][0], s110_0);
                s110_1 = f2fma(q.y, px1[2 * g + 1][1], s110_1);
                s110_2 = f2fma(q.y, px1[2 * g + 1][2], s110_2);
            }
#pragma unroll
            for (int g = 0; g < 8; ++g) {                 // w101
                ulonglong2 q = pwv[16 + g];
                s101_0 = f2fma(q.x, px1[2 * g][0], s101_0);
                s101_1 = f2fma(q.x, px1[2 * g][1], s101_1);
                s101_2 = f2fma(q.x, px1[2 * g][2], s101_2);
                s101_0 = f2fma(q.y, px1[2 * g + 1][0], s101_0);
                s101_1 = f2fma(q.y, px1[2 * g + 1][1], s101_1);
                s101_2 = f2fma(q.y, px1[2 * g + 1][2], s101_2);
            }
#pragma unroll
            for (int g = 0; g < 8; ++g) {                 // w112
                ulonglong2 q = pwv[24 + g];
                s112_0 = f2fma(q.x, px1[2 * g][0], s112_0);
                s112_1 = f2fma(q.x, px1[2 * g][1], s112_1);
                s112_2 = f2fma(q.x, px1[2 * g][2], s112_2);
                s112_0 = f2fma(q.y, px1[2 * g + 1][0], s112_0);
                s112_1 = f2fma(q.y, px1[2 * g + 1][1], s112_1);
                s112_2 = f2fma(q.y, px1[2 * g + 1][2], s112_2);
            }

            // stage-2 operands for dynamic v (SMEM)
            u64 x0v = xs0u[v * T + t];
            ulonglong2 xa = xsA[v * T + t];   // {x1[v][0], x1[v][1]}
            u64 x1v2 = xsB[v * T + t];

            acc00 = f2fma(s000, x0v, acc00);
            acc01 = f2fma(s110_0, xa.x, acc01);
            acc01 = f2fma(s110_1, xa.y, acc01);
            acc01 = f2fma(s110_2, x1v2, acc01);

            a10 = f2fma(s101_0, x0v, a10);
            a11 = f2fma(s101_1, x0v, a11);
            a12 = f2fma(s101_2, x0v, a12);

            P0 = f2fma(s112_0, xa.x, P0);
            P1 = f2fma(s112_1, xa.y, P1);
            P2 = f2fma(s112_2, x1v2, P2);
            Q01 = f2fma(s112_0, xa.y, Q01);
            Q01 = f2fma(s112_1, xa.x, Q01);
            Q02 = f2fma(s112_0, x1v2, Q02);
            Q02 = f2fma(s112_2, xa.x, Q02);
            Q12 = f2fma(s112_1, x1v2, Q12);
            Q12 = f2fma(s112_2, xa.y, Q12);
        }

        // ---- epilogue for this w ----
        const u64 CS2  = fpack(0.31622776601683794f, 0.31622776601683794f); // 1/sqrt(10)
        const u64 C62  = fpack(0.18257418583505536f, 0.18257418583505536f); // 1/sqrt(30)
        const u64 NEG1 = fpack(-1.0f, -1.0f);
        const u64 TWO2 = fpack(2.0f, 2.0f);

        float a, b;
        funpack(f2add(acc00, acc01), a, b);
        outA[w] = a; outB[w] = b;

        funpack(a10, a, b); outA[16 + 3 * w + 0] = a; outB[16 + 3 * w + 0] = b;
        funpack(a11, a, b); outA[16 + 3 * w + 1] = a; outB[16 + 3 * w + 1] = b;
        funpack(a12, a, b); outA[16 + 3 * w + 2] = a; outB[16 + 3 * w + 2] = b;

        funpack(f2mul(CS2, Q01), a, b); outA[64 + 5 * w + 0] = a; outB[64 + 5 * w + 0] = b;
        funpack(f2mul(CS2, Q02), a, b); outA[64 + 5 * w + 1] = a; outB[64 + 5 * w + 1] = b;
        funpack(f2mul(CS2, Q12), a, b); outA[64 + 5 * w + 2] = a; outB[64 + 5 * w + 2] = b;

        u64 d3 = f2fma(P1, NEG1, P0);                 // P0 - P1
        funpack(f2mul(CS2, d3), a, b); outA[64 + 5 * w + 3] = a; outB[64 + 5 * w + 3] = b;

        u64 s01 = f2add(P0, P1);
        u64 d4 = f2fma(TWO2, P2, f2mul(s01, NEG1));   // 2*P2 - P0 - P1
        funpack(f2mul(C62, d4), a, b); outA[64 + 5 * w + 4] = a; outB[64 + 5 * w + 4] = b;
    }
}

extern "C" void kernel_launch(void* const* d_in, const int* in_sizes, int n_in,
                              void* d_out, int out_size) {
    const float* feats = (const float*)d_in[0];
    const float* msgs  = (const float*)d_in[1];
    const float* w000  = (const float*)d_in[2];
    const float* w101  = (const float*)d_in[3];
    const float* w110  = (const float*)d_in[4];
    const float* w112  = (const float*)d_in[5];
    float* out = (float*)d_out;

    const int smem_bytes = 64 * T * (int)sizeof(u64);   // 64 KB
    cudaFuncSetAttribute(e3nn_kernel, cudaFuncAttributeMaxDynamicSharedMemorySize, smem_bytes);

    prep_kernel<<<64, 256>>>(w000, w101, w110, w112);
    e3nn_kernel<<<NNODES / NODES_PER_BLOCK, T, smem_bytes>>>(feats, msgs, out);
}

// round 4
// speedup vs baseline: 2.4020x; 2.4020x over previous
#include <cuda_runtime.h>

// E3nnSimpleNodeBlock: out = TensorSquare(feats+msgs), N=131072, MUL=16.
// Round 3: f32x2 node-pair compute; x0+x1 fully register-resident (v-loop unrolled);
// weights splatted+scaled in global, staged per-w into SMEM (double buffer, cp.async);
// uniform-broadcast LDS.128 weight reads; 2 CTAs/SM, SMEM 16KB -> L1 stays large.

#define T 128
#define NODES_PER_BLOCK 256
#define NNODES 131072

typedef unsigned long long u64;

// Splatted, pre-scaled weights. Layout: [w][v][32 ulonglong2]; each ulonglong2 holds
// two consecutive splatted weights, slot order [000 u0..15 | 110 | 101 | 112]. 128 KB.
__device__ ulonglong2 PW2[16 * 16 * 32];

// ---------- f32x2 helpers ----------
__device__ __forceinline__ u64 f2fma(u64 a, u64 b, u64 c) {
    u64 d;
    asm("fma.rn.f32x2 %0, %1, %2, %3;" : "=l"(d) : "l"(a), "l"(b), "l"(c));
    return d;
}
__device__ __forceinline__ u64 f2add(u64 a, u64 b) {
    u64 d;
    asm("add.rn.f32x2 %0, %1, %2;" : "=l"(d) : "l"(a), "l"(b));
    return d;
}
__device__ __forceinline__ u64 f2mul(u64 a, u64 b) {
    u64 d;
    asm("mul.rn.f32x2 %0, %1, %2;" : "=l"(d) : "l"(a), "l"(b));
    return d;
}
__device__ __forceinline__ u64 fpack(float lo, float hi) {
    u64 d;
    asm("mov.b64 %0, {%1, %2};" : "=l"(d) : "f"(lo), "f"(hi));
    return d;
}
__device__ __forceinline__ void funpack(u64 p, float& lo, float& hi) {
    asm("mov.b64 {%0, %1}, %2;" : "=f"(lo), "=f"(hi) : "l"(p));
}

// ---------- weight prep: transpose + scale + splat, [w][v][slot] ----------
__global__ void prep_kernel(const float* __restrict__ w000, const float* __restrict__ w101,
                            const float* __restrict__ w110, const float* __restrict__ w112) {
    int idx = blockIdx.x * blockDim.x + threadIdx.x;   // 0 .. 16383
    if (idx >= 16 * 16 * 64) return;
    int w = idx >> 10;
    int v = (idx >> 6) & 15;
    int slot = idx & 63;
    int which = slot >> 4, u = slot & 15;
    int widx = u * 256 + v * 16 + w;                   // w[u][v][w], row-major
    const float A000 = 0.04419417382415922f;           // sqrt(1/(2*MUL*MUL))
    const float A110 = 0.02551551815399144f;           // A000/sqrt(3)
    const float A101 = 0.0625f;                        // sqrt(3/MUL^2)/sqrt(3)
    const float A112 = 0.13975424859373686f;           // sqrt(5)/16
    float val;
    if (which == 0)      val = A000 * w000[widx];
    else if (which == 1) val = A110 * w110[widx];
    else if (which == 2) val = A101 * w101[widx];
    else                 val = A112 * w112[widx];
    reinterpret_cast<float2*>(PW2)[idx] = make_float2(val, val);   // splat
}

// ---------- main kernel ----------
__global__ __launch_bounds__(T, 2) void e3nn_kernel(const float* __restrict__ feats,
                                                    const float* __restrict__ msgs,
                                                    float* __restrict__ out) {
    // SMEM: double-buffered per-w weight slab, 512 ull2 each (8 KB), 16 KB total.
    __shared__ ulonglong2 wbuf[2][512];

    const int t = threadIdx.x;
    const int nA = blockIdx.x * NODES_PER_BLOCK + t;
    const int nB = nA + T;

    // ---- load x = feats + msgs for both nodes, pack into f32x2 registers ----
    u64 px0[16];
    u64 px1[16][3];
    {
        float xA[64], xB[64];
        const float4* fA = reinterpret_cast<const float4*>(feats) + nA * 16;
        const float4* mA = reinterpret_cast<const float4*>(msgs) + nA * 16;
        const float4* fB = reinterpret_cast<const float4*>(feats) + nB * 16;
        const float4* mB = reinterpret_cast<const float4*>(msgs) + nB * 16;
#pragma unroll
        for (int q = 0; q < 16; ++q) {
            float4 f = fA[q], m = mA[q];
            xA[4 * q + 0] = f.x + m.x; xA[4 * q + 1] = f.y + m.y;
            xA[4 * q + 2] = f.z + m.z; xA[4 * q + 3] = f.w + m.w;
        }
#pragma unroll
        for (int q = 0; q < 16; ++q) {
            float4 f = fB[q], m = mB[q];
            xB[4 * q + 0] = f.x + m.x; xB[4 * q + 1] = f.y + m.y;
            xB[4 * q + 2] = f.z + m.z; xB[4 * q + 3] = f.w + m.w;
        }
#pragma unroll
        for (int v = 0; v < 16; ++v) px0[v] = fpack(xA[v], xB[v]);
#pragma unroll
        for (int v = 0; v < 16; ++v) {
#pragma unroll
            for (int i = 0; i < 3; ++i) px1[v][i] = fpack(xA[16 + 3 * v + i], xB[16 + 3 * v + i]);
        }
    }

    // ---- cp.async helpers for weight staging (4 x 16B per thread = 8 KB per slab) ----
    const ulonglong2* gw = PW2;
#define STAGE_SLAB(wi, buf)                                                              \
    do {                                                                                 \
        unsigned saddr = (unsigned)__cvta_generic_to_shared(&wbuf[(buf)][t * 4]);        \
        const ulonglong2* src = gw + (wi) * 512 + t * 4;                                 \
        asm volatile("cp.async.cg.shared.global [%0], [%1], 16;" ::"r"(saddr), "l"(src));        \
        asm volatile("cp.async.cg.shared.global [%0], [%1], 16;" ::"r"(saddr + 16), "l"(src + 1)); \
        asm volatile("cp.async.cg.shared.global [%0], [%1], 16;" ::"r"(saddr + 32), "l"(src + 2)); \
        asm volatile("cp.async.cg.shared.global [%0], [%1], 16;" ::"r"(saddr + 48), "l"(src + 3)); \
        asm volatile("cp.async.commit_group;");                                          \
    } while (0)

    // preload slab for w = 0
    STAGE_SLAB(0, 0);
    asm volatile("cp.async.wait_group 0;");
    __syncthreads();

    float* outA = out + (long)nA * 144;
    float* outB = out + (long)nB * 144;

    const u64 CS2  = fpack(0.31622776601683794f, 0.31622776601683794f); // 1/sqrt(10)
    const u64 C62  = fpack(0.18257418583505536f, 0.18257418583505536f); // 1/sqrt(30)
    const u64 NEG1 = fpack(-1.0f, -1.0f);
    const u64 TWO2 = fpack(2.0f, 2.0f);

#pragma unroll 1
    for (int w = 0; w < 16; ++w) {
        // prefetch next slab into the other buffer (that buffer's compute finished last iter)
        if (w < 15) STAGE_SLAB(w + 1, (w + 1) & 1);

        const ulonglong2* __restrict__ cw = wbuf[w & 1];

        u64 acc00 = 0, acc01 = 0;              // out0 paths (000 / 110)
        u64 a10 = 0, a11 = 0, a12 = 0;         // out1 k=0..2
        u64 P0 = 0, P1 = 0, P2 = 0;            // out2 diagonal sums
        u64 Q01 = 0, Q02 = 0, Q12 = 0;         // out2 cross sums

#pragma unroll
        for (int v = 0; v < 16; ++v) {
            const ulonglong2* __restrict__ pwv = cw + v * 32;   // uniform (broadcast) LDS

            u64 s000 = 0;
            u64 s110_0 = 0, s110_1 = 0, s110_2 = 0;
            u64 s101_0 = 0, s101_1 = 0, s101_2 = 0;
            u64 s112_0 = 0, s112_1 = 0, s112_2 = 0;

#pragma unroll
            for (int g = 0; g < 8; ++g) {                 // w000
                ulonglong2 q = pwv[g];
                s000 = f2fma(q.x, px0[2 * g + 0], s000);
                s000 = f2fma(q.y, px0[2 * g + 1], s000);
            }
#pragma unroll
            for (int g = 0; g < 8; ++g) {                 // w110
                ulonglong2 q = pwv[8 + g];
                s110_0 = f2fma(q.x, px1[2 * g][0], s110_0);
                s110_1 = f2fma(q.x, px1[2 * g][1], s110_1);
                s110_2 = f2fma(q.x, px1[2 * g][2], s110_2);
                s110_0 = f2fma(q.y, px1[2 * g + 1][0], s110_0);
                s110_1 = f2fma(q.y, px1[2 * g + 1][1], s110_1);
                s110_2 = f2fma(q.y, px1[2 * g + 1][2], s110_2);
            }
#pragma unroll
            for (int g = 0; g < 8; ++g) {                 // w101
                ulonglong2 q = pwv[16 + g];
                s101_0 = f2fma(q.x, px1[2 * g][0], s101_0);
                s101_1 = f2fma(q.x, px1[2 * g][1], s101_1);
                s101_2 = f2fma(q.x, px1[2 * g][2], s101_2);
                s101_0 = f2fma(q.y, px1[2 * g + 1][0], s101_0);
                s101_1 = f2fma(q.y, px1[2 * g + 1][1], s101_1);
                s101_2 = f2fma(q.y, px1[2 * g + 1][2], s101_2);
            }
#pragma unroll
            for (int g = 0; g < 8; ++g) {                 // w112
                ulonglong2 q = pwv[24 + g];
                s112_0 = f2fma(q.x, px1[2 * g][0], s112_0);
                s112_1 = f2fma(q.x, px1[2 * g][1], s112_1);
                s112_2 = f2fma(q.x, px1[2 * g][2], s112_2);
                s112_0 = f2fma(q.y, px1[2 * g + 1][0], s112_0);
                s112_1 = f2fma(q.y, px1[2 * g + 1][1], s112_1);
                s112_2 = f2fma(q.y, px1[2 * g + 1][2], s112_2);
            }

            // stage-2: v is static -> register-direct operands
            acc00 = f2fma(s000, px0[v], acc00);
            acc01 = f2fma(s110_0, px1[v][0], acc01);
            acc01 = f2fma(s110_1, px1[v][1], acc01);
            acc01 = f2fma(s110_2, px1[v][2], acc01);

            a10 = f2fma(s101_0, px0[v], a10);
            a11 = f2fma(s101_1, px0[v], a11);
            a12 = f2fma(s101_2, px0[v], a12);

            P0 = f2fma(s112_0, px1[v][0], P0);
            P1 = f2fma(s112_1, px1[v][1], P1);
            P2 = f2fma(s112_2, px1[v][2], P2);
            Q01 = f2fma(s112_0, px1[v][1], Q01);
            Q01 = f2fma(s112_1, px1[v][0], Q01);
            Q02 = f2fma(s112_0, px1[v][2], Q02);
            Q02 = f2fma(s112_2, px1[v][0], Q02);
            Q12 = f2fma(s112_1, px1[v][2], Q12);
            Q12 = f2fma(s112_2, px1[v][1], Q12);
        }

        // ---- epilogue for this w ----
        float a, b;
        funpack(f2add(acc00, acc01), a, b);
        outA[w] = a; outB[w] = b;

        funpack(a10, a, b); outA[16 + 3 * w + 0] = a; outB[16 + 3 * w + 0] = b;
        funpack(a11, a, b); outA[16 + 3 * w + 1] = a; outB[16 + 3 * w + 1] = b;
        funpack(a12, a, b); outA[16 + 3 * w + 2] = a; outB[16 + 3 * w + 2] = b;

        funpack(f2mul(CS2, Q01), a, b); outA[64 + 5 * w + 0] = a; outB[64 + 5 * w + 0] = b;
        funpack(f2mul(CS2, Q02), a, b); outA[64 + 5 * w + 1] = a; outB[64 + 5 * w + 1] = b;
        funpack(f2mul(CS2, Q12), a, b); outA[64 + 5 * w + 2] = a; outB[64 + 5 * w + 2] = b;

        u64 d3 = f2fma(P1, NEG1, P0);                 // P0 - P1
        funpack(f2mul(CS2, d3), a, b); outA[64 + 5 * w + 3] = a; outB[64 + 5 * w + 3] = b;

        u64 s01 = f2add(P0, P1);
        u64 d4 = f2fma(TWO2, P2, f2mul(s01, NEG1));   // 2*P2 - P0 - P1
        funpack(f2mul(C62, d4), a, b); outA[64 + 5 * w + 4] = a; outB[64 + 5 * w + 4] = b;

        // next slab staged; make it visible to all warps before next iteration reads it
        asm volatile("cp.async.wait_group 0;");
        __syncthreads();
    }
#undef STAGE_SLAB
}

extern "C" void kernel_launch(void* const* d_in, const int* in_sizes, int n_in,
                              void* d_out, int out_size) {
    const float* feats = (const float*)d_in[0];
    const float* msgs  = (const float*)d_in[1];
    const float* w000  = (const float*)d_in[2];
    const float* w101  = (const float*)d_in[3];
    const float* w110  = (const float*)d_in[4];
    const float* w112  = (const float*)d_in[5];
    float* out = (float*)d_out;

    prep_kernel<<<64, 256>>>(w000, w101, w110, w112);
    e3nn_kernel<<<NNODES / NODES_PER_BLOCK, T>>>(feats, msgs, out);
}